// round 11
// baseline (speedup 1.0000x reference)
#include <cuda_runtime.h>
#include <cstdint>

// Output: [B=4, D=160, H=192, W=224, 3] float32, contiguous, 330 MB.
// out[b,d,h,w,i] = A[b,i,0]*x + A[b,i,1]*y + A[b,i,2]*z + t[b,i] - mesh_i
// with x = d - 79.5, y = h - 95.5, z = w - 111.5.
//
// R7 result: TMA bulk store bypassing L1TEX -> 48.8us, DRAM 74%.
// R8 change: 24KB tile per CTA, emitted as TWO 12KB bulk copies. The first
// copy is committed while the second half is still being computed, halving
// per-CTA sync/issue overhead and deepening bulk-copy pipelining.

#define DD 160
#define HH 192
#define WW 224
#define CHUNKS_PER_ROW 56                              // (WW*3)/12
#define TOTAL_CHUNKS (4 * DD * HH * CHUNKS_PER_ROW)    // 6,881,280
#define CHUNKS_PER_CTA 512
#define HALF_FLOATS 3072                               // 256 chunks * 12
#define HALF_BYTES  12288
#define TILE_FLOATS 6144                               // 24 KB

__device__ __forceinline__ uint32_t smem_u32(const void* p) {
    uint32_t a;
    asm("{ .reg .u64 t; cvta.to.shared.u64 t, %1; cvt.u32.u64 %0, t; }"
        : "=r"(a) : "l"(p));
    return a;
}

__device__ __forceinline__ void compute_chunk(const float* __restrict__ M,
                                              unsigned c, float4* s) {
    unsigned row = c / CHUNKS_PER_ROW;          // b*D*H + d*H + h
    unsigned wc  = c - row * CHUNKS_PER_ROW;
    unsigned b   = row / (DD * HH);
    unsigned rem = row - b * (DD * HH);
    unsigned d   = rem / HH;
    unsigned h   = rem - d * HH;

    float x  = (float)d - 79.5f;
    float y  = (float)h - 95.5f;
    float w0 = (float)(wc * 4u) - 111.5f;

    const float4* Mb = (const float4*)(M + b * 12u);
    float4 r0 = __ldg(Mb + 0);   // A00 A01 A02 t0
    float4 r1 = __ldg(Mb + 1);   // A10 A11 A12 t1
    float4 r2 = __ldg(Mb + 2);   // A20 A21 A22 t2

    float base0 = fmaf(r0.x, x, fmaf(r0.y, y, r0.w)) - x;
    float base1 = fmaf(r1.x, x, fmaf(r1.y, y, r1.w)) - y;
    float base2 = fmaf(r2.x, x, fmaf(r2.y, y, r2.w));

    float v[12];
#pragma unroll
    for (int k = 0; k < 4; k++) {
        float z = w0 + (float)k;
        v[3 * k + 0] = fmaf(r0.z, z, base0);
        v[3 * k + 1] = fmaf(r1.z, z, base1);
        v[3 * k + 2] = fmaf(r2.z, z, base2) - z;
    }
    s[0] = make_float4(v[0], v[1], v[2],  v[3]);
    s[1] = make_float4(v[4], v[5], v[6],  v[7]);
    s[2] = make_float4(v[8], v[9], v[10], v[11]);
}

__global__ __launch_bounds__(256)
void AffineToDenseShift_kernel(const float* __restrict__ M,
                               float* __restrict__ out) {
    __shared__ __align__(128) float tile[TILE_FLOATS];

    unsigned tid  = threadIdx.x;
    unsigned base = blockIdx.x * (unsigned)CHUNKS_PER_CTA;

    // ---- first half: chunks [base, base+256) ----
    compute_chunk(M, base + tid, (float4*)(tile + tid * 12u));

    __syncthreads();
    asm volatile("fence.proxy.async.shared::cta;" ::: "memory");

    uint32_t saddr = smem_u32(tile);
    uint64_t gaddr = (uint64_t)(uintptr_t)out + (uint64_t)base * 48u;
    if (tid == 0) {
        asm volatile(
            "cp.async.bulk.global.shared::cta.bulk_group [%0], [%1], %2;"
            :: "l"(gaddr), "r"(saddr), "n"(HALF_BYTES) : "memory");
        asm volatile("cp.async.bulk.commit_group;" ::: "memory");
    }

    // ---- second half: chunks [base+256, base+512), overlaps copy 0 ----
    compute_chunk(M, base + 256u + tid,
                  (float4*)(tile + HALF_FLOATS + tid * 12u));

    __syncthreads();
    asm volatile("fence.proxy.async.shared::cta;" ::: "memory");

    if (tid == 0) {
        asm volatile(
            "cp.async.bulk.global.shared::cta.bulk_group [%0], [%1], %2;"
            :: "l"(gaddr + (uint64_t)HALF_BYTES),
               "r"(saddr + (uint32_t)HALF_BYTES), "n"(HALF_BYTES) : "memory");
        asm volatile("cp.async.bulk.commit_group;" ::: "memory");
        // SMEM is freed at CTA exit; both copies must have read out by then.
        asm volatile("cp.async.bulk.wait_group 0;" ::: "memory");
    }
    __syncthreads();
}

extern "C" void kernel_launch(void* const* d_in, const int* in_sizes, int n_in,
                              void* d_out, int out_size) {
    const float* M = (const float*)d_in[0];
    float* out = (float*)d_out;
    int blocks = TOTAL_CHUNKS / CHUNKS_PER_CTA;   // 13440, exact
    AffineToDenseShift_kernel<<<blocks, 256>>>(M, out);
}